// round 15
// baseline (speedup 1.0000x reference)
#include <cuda_runtime.h>
#include <cuda_fp16.h>
#include <math.h>
#include <stdint.h>

#define S_LEN  3072
#define DIM_   2048
#define NH     16
#define HD     128
#define C_HALF 64
#define GF 8
#define GH 16
#define GW 24
#define CF 22
#define CH 21
#define LDK 136   // flash smem leading dim (128 + 8 pad)

// ---------------- scratch ----------------------------------------------------
__device__ float  g_Q[(size_t)S_LEN * DIM_];
__device__ float  g_K[(size_t)S_LEN * DIM_];
__device__ __half g_xh[(size_t)S_LEN * DIM_];
__device__ __half g_Wqh[(size_t)DIM_ * DIM_];
__device__ __half g_Wkh[(size_t)DIM_ * DIM_];
__device__ __half g_Wvh[(size_t)DIM_ * DIM_];
__device__ __half g_Woh[(size_t)DIM_ * DIM_];
__device__ __half g_Qh[(size_t)S_LEN * DIM_];
__device__ __half g_Kh[(size_t)S_LEN * DIM_];
__device__ __half g_Vh[(size_t)S_LEN * DIM_];
__device__ __half g_Oh[(size_t)S_LEN * DIM_];
__device__ float  g_cos[S_LEN * C_HALF];
__device__ float  g_sin[S_LEN * C_HALF];

// ---------------- small kernels ----------------------------------------------
__global__ void cvt5_kernel(const float* __restrict__ X,
                            const float* __restrict__ W0, const float* __restrict__ W1,
                            const float* __restrict__ W2, const float* __restrict__ W3,
                            __half* __restrict__ OX,
                            __half* __restrict__ O0, __half* __restrict__ O1,
                            __half* __restrict__ O2, __half* __restrict__ O3,
                            int nx4, int nw4) {
    int i = blockIdx.x * blockDim.x + threadIdx.x;
    int z = blockIdx.y;
    const float* in;
    __half* out;
    int n;
    if (z == 0)      { in = X;  out = OX; n = nx4; }
    else if (z == 1) { in = W0; out = O0; n = nw4; }
    else if (z == 2) { in = W1; out = O1; n = nw4; }
    else if (z == 3) { in = W2; out = O2; n = nw4; }
    else             { in = W3; out = O3; n = nw4; }
    if (i >= n) return;
    float4 v = ((const float4*)in)[i];
    ((half2*)out)[2 * i]     = __floats2half2_rn(v.x, v.y);
    ((half2*)out)[2 * i + 1] = __floats2half2_rn(v.z, v.w);
}

__global__ void rope_table_kernel(const float* __restrict__ fa,
                                  float* __restrict__ ctab,
                                  float* __restrict__ stab) {
    int idx = blockIdx.x * blockDim.x + threadIdx.x;
    if (idx >= S_LEN * C_HALF) return;
    int s = idx >> 6;
    int j = idx & 63;
    int f = s / (GH * GW);
    int h = (s / GW) % GH;
    int w = s % GW;
    int row = (j < CF) ? f : (j < CF + CH) ? h : w;
    float a = fa[row * C_HALF + j];
    ctab[idx] = cosf(a);
    stab[idx] = sinf(a);
}

// grid (S_LEN, 2): z=0 -> Q (scaled), z=1 -> K
__global__ void rms_rope_kernel(const float* __restrict__ inQ,
                                const float* __restrict__ inK,
                                __half* __restrict__ outQ,
                                __half* __restrict__ outK,
                                const float* __restrict__ gq,
                                const float* __restrict__ gk,
                                const float* __restrict__ ctab,
                                const float* __restrict__ stab,
                                float scaleQ) {
    int s = blockIdx.x;
    int z = blockIdx.y;
    const float* row = ((z == 0) ? inQ : inK) + (size_t)s * DIM_;
    half2* orow = (half2*)(((z == 0) ? outQ : outK) + (size_t)s * DIM_);
    const float* g = (z == 0) ? gq : gk;
    float scale = (z == 0) ? scaleQ : 1.0f;
    int tid = threadIdx.x;

    float ss = 0.f;
    #pragma unroll
    for (int i = tid; i < DIM_; i += 256) {
        float v = row[i];
        ss += v * v;
    }
    __shared__ float red[256];
    red[tid] = ss;
    __syncthreads();
    #pragma unroll
    for (int off = 128; off > 0; off >>= 1) {
        if (tid < off) red[tid] += red[tid + off];
        __syncthreads();
    }
    float inv = rsqrtf(red[0] * (1.0f / DIM_) + 1e-6f) * scale;

    const float* crow = ctab + s * C_HALF;
    const float* srow = stab + s * C_HALF;
    #pragma unroll
    for (int p = tid; p < DIM_ / 2; p += 256) {
        int j = p & (C_HALF - 1);
        float c = crow[j], sn = srow[j];
        float te = row[2 * p]     * inv * g[2 * p];
        float to = row[2 * p + 1] * inv * g[2 * p + 1];
        orow[p] = __floats2half2_rn(te * c - to * sn, te * sn + to * c);
    }
}

// ---------------- cp.async / mma helpers -------------------------------------
__device__ __forceinline__ void cp_async16(void* smem, const void* gmem) {
    unsigned s = (unsigned)__cvta_generic_to_shared(smem);
    asm volatile("cp.async.cg.shared.global [%0], [%1], 16;\n"
                 :: "r"(s), "l"(gmem));
}
__device__ __forceinline__ void cp_commit() {
    asm volatile("cp.async.commit_group;\n");
}
template <int N>
__device__ __forceinline__ void cp_wait() {
    asm volatile("cp.async.wait_group %0;\n" :: "n"(N));
}

__device__ __forceinline__ void mma16816(float* c, const unsigned* a,
                                         const unsigned* b) {
    asm volatile("mma.sync.aligned.m16n8k16.row.col.f32.f16.f16.f32 "
                 "{%0,%1,%2,%3}, {%4,%5,%6,%7}, {%8,%9}, {%0,%1,%2,%3};\n"
                 : "+f"(c[0]), "+f"(c[1]), "+f"(c[2]), "+f"(c[3])
                 : "r"(a[0]), "r"(a[1]), "r"(a[2]), "r"(a[3]),
                   "r"(b[0]), "r"(b[1]));
}
__device__ __forceinline__ void ldsm_x4(unsigned* r, unsigned a) {
    asm volatile("ldmatrix.sync.aligned.m8n8.x4.shared.b16 {%0,%1,%2,%3}, [%4];\n"
                 : "=r"(r[0]), "=r"(r[1]), "=r"(r[2]), "=r"(r[3]) : "r"(a));
}
__device__ __forceinline__ void ldsm_x2(unsigned* r, unsigned a) {
    asm volatile("ldmatrix.sync.aligned.m8n8.x2.shared.b16 {%0,%1}, [%2];\n"
                 : "=r"(r[0]), "=r"(r[1]) : "r"(a));
}
__device__ __forceinline__ void ldsm_x2t(unsigned* r, unsigned a) {
    asm volatile("ldmatrix.sync.aligned.m8n8.x2.trans.shared.b16 {%0,%1}, [%2];\n"
                 : "=r"(r[0]), "=r"(r[1]) : "r"(a));
}
__device__ __forceinline__ unsigned packh2(float a, float b) {
    half2 h = __floats2half2_rn(a, b);
    return *(unsigned*)&h;
}

// ---------------- mma.sync GEMM NT (round-8 proven: 3-stage, bottom barrier) -
#define GSTG 3
#define GLD 40
#define GSLOT (2 * 128 * GLD)
#define GEMM_SMEM (GSTG * GSLOT * 2)  // 61440 bytes

__global__ __launch_bounds__(256, 2)
void gemm_mma(const __half* __restrict__ A,
              const __half* __restrict__ B0, const __half* __restrict__ B1,
              const __half* __restrict__ B2,
              const float* __restrict__ bias0, const float* __restrict__ bias1,
              const float* __restrict__ bias2,
              float* __restrict__ Cf0, float* __restrict__ Cf1,
              __half* __restrict__ Ch2) {
    extern __shared__ __half gsm[];
    int z = blockIdx.z;
    const __half* Bw = (z == 0) ? B0 : (z == 1) ? B1 : B2;
    const float* bias = (z == 0) ? bias0 : (z == 1) ? bias1 : bias2;

    int m0 = blockIdx.y * 128, n0 = blockIdx.x * 128;
    int tid = threadIdx.x;
    int w = tid >> 5, lane = tid & 31;
    int wm = w & 3, wn = w >> 2;

    int lr = tid >> 2, lc = (tid & 3) << 3;
    const __half* gA = A + (size_t)(m0 + lr) * DIM_ + lc;
    const __half* gB = Bw + (size_t)(n0 + lr) * DIM_ + lc;
    unsigned sbase = (unsigned)__cvta_generic_to_shared(gsm);

    int a_r = (lane & 7) + (lane & 8);
    int a_c = (lane & 16) >> 1;
    int b_r = (lane & 7) + (((lane >> 4) & 1) << 3);
    int b_c = ((lane >> 3) & 1) << 3;

    float cacc[2][8][4];
    #pragma unroll
    for (int i = 0; i < 2; ++i)
        #pragma unroll
        for (int f = 0; f < 8; ++f)
            cacc[i][f][0] = cacc[i][f][1] = cacc[i][f][2] = cacc[i][f][3] = 0.f;

    const int nk = DIM_ / 32;   // 64

    #pragma unroll
    for (int c = 0; c < 2; ++c) {
        __half* sA = gsm + c * GSLOT;
        __half* sB = sA + 128 * GLD;
        int kofs = c * 32;
        cp_async16(sA + lr * GLD + lc, gA + kofs);
        cp_async16(sA + (lr + 64) * GLD + lc, gA + kofs + (size_t)64 * DIM_);
        cp_async16(sB + lr * GLD + lc, gB + kofs);
        cp_async16(sB + (lr + 64) * GLD + lc, gB + kofs + (size_t)64 * DIM_);
        cp_commit();
    }

    for (int it = 0; it < nk; ++it) {
        if (it + 1 < nk) cp_wait<1>(); else cp_wait<0>();
        __syncthreads();

        if (it + 2 < nk) {
            int sl = (it + 2) % GSTG;
            __half* sA = gsm + sl * GSLOT;
            __half* sB = sA + 128 * GLD;
            int kofs = (it + 2) * 32;
            cp_async16(sA + lr * GLD + lc, gA + kofs);
            cp_async16(sA + (lr + 64) * GLD + lc, gA + kofs + (size_t)64 * DIM_);
            cp_async16(sB + lr * GLD + lc, gB + kofs);
            cp_async16(sB + (lr + 64) * GLD + lc, gB + kofs + (size_t)64 * DIM_);
            cp_commit();
        }

        unsigned abase = sbase + (unsigned)((it % GSTG) * GSLOT) * 2;
        unsigned bbase = abase + 128 * GLD * 2;
        #pragma unroll
        for (int kb = 0; kb < 32; kb += 16) {
            unsigned af[2][4];
            #pragma unroll
            for (int i = 0; i < 2; ++i)
                ldsm_x4(af[i], abase +
                    (unsigned)(((wm * 32 + i * 16 + a_r) * GLD) + kb + a_c) * 2);
            #pragma unroll
            for (int jj = 0; jj < 4; ++jj) {
                unsigned bf[4];
                ldsm_x4(bf, bbase +
                    (unsigned)(((wn * 64 + jj * 16 + b_r) * GLD) + kb + b_c) * 2);
                #pragma unroll
                for (int i = 0; i < 2; ++i) {
                    mma16816(cacc[i][jj * 2],     af[i], &bf[0]);
                    mma16816(cacc[i][jj * 2 + 1], af[i], &bf[2]);
                }
            }
        }
        __syncthreads();
    }

    int g = lane >> 2, qp = lane & 3;
    #pragma unroll
    for (int i = 0; i < 2; ++i) {
        int r0 = m0 + wm * 32 + i * 16 + g;
        #pragma unroll
        for (int f = 0; f < 8; ++f) {
            int jj = f >> 1, hf = f & 1;
            int col = n0 + wn * 64 + jj * 16 + hf * 8 + qp * 2;
            float b0 = bias[col], b1 = bias[col + 1];
            float* cc = cacc[i][f];
            if (z == 2) {
                *(half2*)&Ch2[(size_t)r0 * DIM_ + col] =
                    __floats2half2_rn(cc[0] + b0, cc[1] + b1);
                *(half2*)&Ch2[(size_t)(r0 + 8) * DIM_ + col] =
                    __floats2half2_rn(cc[2] + b0, cc[3] + b1);
            } else {
                float* Cf = (z == 0) ? Cf0 : Cf1;
                float2 v0 = {cc[0] + b0, cc[1] + b1};
                float2 v1 = {cc[2] + b0, cc[3] + b1};
                *(float2*)&Cf[(size_t)r0 * DIM_ + col] = v0;
                *(float2*)&Cf[(size_t)(r0 + 8) * DIM_ + col] = v1;
            }
        }
    }
}

// ---------------- GEMM NT, M-tile 64 (for out-proj makespan) ------------------
// block 64x128, 8 warps (4m x 2n), warp tile 16x64, k-step 32, 3-stage pipe.
#define G64SLOT ((64 + 128) * GLD)
#define GEMM64_SMEM (GSTG * G64SLOT * 2)  // 46080 bytes

__global__ __launch_bounds__(256, 2)
void gemm_mma64(const __half* __restrict__ A, const __half* __restrict__ B,
                const float* __restrict__ bias, float* __restrict__ C) {
    extern __shared__ __half gsm[];
    int m0 = blockIdx.y * 64, n0 = blockIdx.x * 128;
    int tid = threadIdx.x;
    int w = tid >> 5, lane = tid & 31;
    int wm = w & 3, wn = w >> 2;

    int lr = tid >> 2, lc = (tid & 3) << 3;
    const __half* gA = A + (size_t)(m0 + lr) * DIM_ + lc;
    const __half* gB = B + (size_t)(n0 + lr) * DIM_ + lc;
    unsigned sbase = (unsigned)__cvta_generic_to_shared(gsm);

    int a_r = (lane & 7) + (lane & 8);
    int a_c = (lane & 16) >> 1;
    int b_r = (lane & 7) + (((lane >> 4) & 1) << 3);
    int b_c = ((lane >> 3) & 1) << 3;

    float cacc[8][4];
    #pragma unroll
    for (int f = 0; f < 8; ++f)
        cacc[f][0] = cacc[f][1] = cacc[f][2] = cacc[f][3] = 0.f;

    const int nk = DIM_ / 32;   // 64

    #pragma unroll
    for (int c = 0; c < 2; ++c) {
        __half* sA = gsm + c * G64SLOT;
        __half* sB = sA + 64 * GLD;
        int kofs = c * 32;
        cp_async16(sA + lr * GLD + lc, gA + kofs);
        cp_async16(sB + lr * GLD + lc, gB + kofs);
        cp_async16(sB + (lr + 64) * GLD + lc, gB + kofs + (size_t)64 * DIM_);
        cp_commit();
    }

    for (int it = 0; it < nk; ++it) {
        if (it + 1 < nk) cp_wait<1>(); else cp_wait<0>();
        __syncthreads();

        if (it + 2 < nk) {
            int sl = (it + 2) % GSTG;
            __half* sA = gsm + sl * G64SLOT;
            __half* sB = sA + 64 * GLD;
            int kofs = (it + 2) * 32;
            cp_async16(sA + lr * GLD + lc, gA + kofs);
            cp_async16(sB + lr * GLD + lc, gB + kofs);
            cp_async16(sB + (lr + 64) * GLD + lc, gB + kofs + (size_t)64 * DIM_);
            cp_commit();
        }

        unsigned abase = sbase + (unsigned)((it % GSTG) * G64SLOT) * 2;
        unsigned bbase = abase + 64 * GLD * 2;
        #pragma unroll
        for (int kb = 0; kb < 32; kb += 16) {
            unsigned af[4];
            ldsm_x4(af, abase +
                (unsigned)(((wm * 16 + a_r) * GLD) + kb + a_c) * 2);
            #pragma unroll
            for (int jj = 0; jj < 4; ++jj) {
                unsigned bf[4];
                ldsm_x4(bf, bbase +
                    (unsigned)(((wn * 64 + jj * 16 + b_r) * GLD) + kb + b_c) * 2);
                mma16816(cacc[jj * 2],     af, &bf[0]);
                mma16816(cacc[jj * 2 + 1], af, &bf[2]);
            }
        }
        __syncthreads();
    }

    int g = lane >> 2, qp = lane & 3;
    int r0 = m0 + wm * 16 + g;
    #pragma unroll
    for (int f = 0; f < 8; ++f) {
        int jj = f >> 1, hf = f & 1;
        int col = n0 + wn * 64 + jj * 16 + hf * 8 + qp * 2;
        float b0 = bias[col], b1 = bias[col + 1];
        float* cc = cacc[f];
        float2 v0 = {cc[0] + b0, cc[1] + b1};
        float2 v1 = {cc[2] + b0, cc[3] + b1};
        *(float2*)&C[(size_t)r0 * DIM_ + col] = v0;
        *(float2*)&C[(size_t)(r0 + 8) * DIM_ + col] = v1;
    }
}

// ---------------- flash attention kernel -------------------------------------
// 128 threads (4 warps), Q-tile 64, 3 CTAs/SM (12 warps/SM). Register Q+O.
#define FLASH_SMEM (4 * 64 * LDK * 2)   // 69632 bytes

__global__ __launch_bounds__(128, 3)
void flash_kernel(const __half* __restrict__ Q, const __half* __restrict__ K,
                  const __half* __restrict__ V, __half* __restrict__ O) {
    extern __shared__ __half sm[];
    __half* sK = sm;
    __half* sV = sm + 2 * 64 * LDK;

    int q0 = blockIdx.x * 64;
    int h  = blockIdx.y;
    int tid = threadIdx.x;
    int w = tid >> 5, lane = tid & 31;
    int g = lane >> 2, qp = lane & 3;
    int wm0 = w * 16;

    const __half* Qg = Q + (size_t)q0 * DIM_ + h * HD;
    const __half* Kg = K + h * HD;
    const __half* Vg = V + h * HD;

    // stage Q (64x128) into sK region, extract A fragments
    #pragma unroll
    for (int it = 0; it < 8; ++it) {
        int slot = tid + it * 128;
        int r = slot >> 4, c = (slot & 15) << 3;
        cp_async16(&sK[r * LDK + c], Qg + (size_t)r * DIM_ + c);
    }
    cp_commit();
    cp_wait<0>();
    __syncthreads();

    unsigned qf[8][4];
    {
        unsigned base = (unsigned)__cvta_generic_to_shared(sK);
        int row = wm0 + (lane & 7) + (lane & 8);
        #pragma unroll
        for (int kk = 0; kk < 8; ++kk) {
            int col = kk * 16 + ((lane & 16) >> 1);
            ldsm_x4(qf[kk], base + (row * LDK + col) * 2);
        }
    }
    __syncthreads();

    float oacc[16][4];
    #pragma unroll
    for (int t = 0; t < 16; ++t)
        #pragma unroll
        for (int c = 0; c < 4; ++c) oacc[t][c] = 0.f;
    float mA = -1e30f, mB = -1e30f, lA = 0.f, lB = 0.f;

    #pragma unroll
    for (int it = 0; it < 8; ++it) {
        int slot = tid + it * 128;
        int r = slot >> 4, c = (slot & 15) << 3;
        cp_async16(&sK[r * LDK + c], Kg + (size_t)r * DIM_ + c);
        cp_async16(&sV[r * LDK + c], Vg + (size_t)r * DIM_ + c);
    }
    cp_commit();

    const int NCH = S_LEN / 64;
    for (int i = 0; i < NCH; ++i) {
        cp_wait<0>();
        __syncthreads();

        if (i + 1 < NCH) {
            int st = (i + 1) & 1;
            const __half* kg = Kg + (size_t)(i + 1) * 64 * DIM_;
            const __half* vg = Vg + (size_t)(i + 1) * 64 * DIM_;
            __half* dK = sK + st * 64 * LDK;
            __half* dV = sV + st * 64 * LDK;
            #pragma unroll
            for (int it = 0; it < 8; ++it) {
                int slot = tid + it * 128;
                int r = slot >> 4, c = (slot & 15) << 3;
                cp_async16(&dK[r * LDK + c], kg + (size_t)r * DIM_ + c);
                cp_async16(&dV[r * LDK + c], vg + (size_t)r * DIM_ + c);
            }
            cp_commit();
        }

        int st = i & 1;
        unsigned kbase = (unsigned)__cvta_generic_to_shared(sK + st * 64 * LDK);
        unsigned vbase = (unsigned)__cvta_generic_to_shared(sV + st * 64 * LDK);

        float sacc[8][4];
        #pragma unroll
        for (int j = 0; j < 8; ++j)
            sacc[j][0] = sacc[j][1] = sacc[j][2] = sacc[j][3] = 0.f;
        #pragma unroll
        for (int j = 0; j < 8; ++j) {
            int krow = 8 * j + (lane & 7);
            #pragma unroll
            for (int kk = 0; kk < 8; ++kk) {
                unsigned b[2];
                int kcol = 16 * kk + (lane & 8);
                ldsm_x2(b, kbase + (krow * LDK + kcol) * 2);
                mma16816(sacc[j], qf[kk], b);
            }
        }

        float cmA = -1e30f, cmB = -1e30f;
        #pragma unroll
        for (int j = 0; j < 8; ++j) {
            cmA = fmaxf(cmA, fmaxf(sacc[j][0], sacc[j][1]));
            cmB = fmaxf(cmB, fmaxf(sacc[j][2], sacc[j][3]));
        }
        cmA = fmaxf(cmA, __shfl_xor_sync(0xffffffffu, cmA, 1));
        cmA = fmaxf(cmA, __shfl_xor_sync(0xffffffffu, cmA, 2));
        cmB = fmaxf(cmB, __shfl_xor_sync(0xffffffffu, cmB, 1));
        cmB = fmaxf(cmB, __shfl_xor_sync(0xffffffffu, cmB, 2));
        float mAn = fmaxf(mA, cmA), mBn = fmaxf(mB, cmB);
        float fA = __expf(mA - mAn), fB = __expf(mB - mBn);

        float sumA = 0.f, sumB = 0.f;
        #pragma unroll
        for (int j = 0; j < 8; ++j) {
            sacc[j][0] = __expf(sacc[j][0] - mAn);
            sacc[j][1] = __expf(sacc[j][1] - mAn);
            sacc[j][2] = __expf(sacc[j][2] - mBn);
            sacc[j][3] = __expf(sacc[j][3] - mBn);
            sumA += sacc[j][0] + sacc[j][1];
            sumB += sacc[j][2] + sacc[j][3];
        }
        sumA += __shfl_xor_sync(0xffffffffu, sumA, 1);
        sumA += __shfl_xor_sync(0xffffffffu, sumA, 2);
        sumB += __shfl_xor_sync(0xffffffffu, sumB, 1);
        sumB += __shfl_xor_sync(0xffffffffu, sumB, 2);
        lA = lA * fA + sumA;
        lB = lB * fB + sumB;
        mA = mAn; mB = mBn;

        #pragma unroll
        for (int t = 0; t < 16; ++t) {
            oacc[t][0] *= fA; oacc[t][1] *= fA;
            oacc[t][2] *= fB; oacc[t][3] *= fB;
        }

        unsigned pf[4][4];
        #pragma unroll
        for (int kt = 0; kt < 4; ++kt) {
            pf[kt][0] = packh2(sacc[2 * kt][0],     sacc[2 * kt][1]);
            pf[kt][1] = packh2(sacc[2 * kt][2],     sacc[2 * kt][3]);
            pf[kt][2] = packh2(sacc[2 * kt + 1][0], sacc[2 * kt + 1][1]);
            pf[kt][3] = packh2(sacc[2 * kt + 1][2], sacc[2 * kt + 1][3]);
        }

        #pragma unroll
        for (int t = 0; t < 16; ++t) {
            #pragma unroll
            for (int kt = 0; kt < 4; ++kt) {
                unsigned b[2];
                int vrow = 16 * kt + (lane & 15);
                ldsm_x2t(b, vbase + (vrow * LDK + 8 * t) * 2);
                mma16816(oacc[t], pf[kt], b);
            }
        }
    }

    float invA = 1.f / lA, invB = 1.f / lB;
    size_t b0 = (size_t)(q0 + wm0 + g) * DIM_ + h * HD + qp * 2;
    size_t b1 = b0 + (size_t)8 * DIM_;
    #pragma unroll
    for (int t = 0; t < 16; ++t) {
        *(half2*)&O[b0 + 8 * t] =
            __floats2half2_rn(oacc[t][0] * invA, oacc[t][1] * invA);
        *(half2*)&O[b1 + 8 * t] =
            __floats2half2_rn(oacc[t][2] * invB, oacc[t][3] * invB);
    }
}

// ---------------- launch ------------------------------------------------------
extern "C" void kernel_launch(void* const* d_in, const int* in_sizes, int n_in,
                              void* d_out, int out_size) {
    const float* x   = (const float*)d_in[0];
    const float* fa  = (const float*)d_in[1];
    const float* Wq  = (const float*)d_in[2];
    const float* bq  = (const float*)d_in[3];
    const float* Wk  = (const float*)d_in[4];
    const float* bk  = (const float*)d_in[5];
    const float* Wv  = (const float*)d_in[6];
    const float* bv  = (const float*)d_in[7];
    const float* Wo  = (const float*)d_in[8];
    const float* bo  = (const float*)d_in[9];
    const float* gq  = (const float*)d_in[10];
    const float* gk  = (const float*)d_in[11];
    float* out = (float*)d_out;

    float *Qp, *Kp, *Cp, *Sn;
    __half *xh, *Wqh, *Wkh, *Wvh, *Woh, *Qh, *Kh, *Vh, *Oh;
    cudaGetSymbolAddress((void**)&Qp, g_Q);
    cudaGetSymbolAddress((void**)&Kp, g_K);
    cudaGetSymbolAddress((void**)&Cp, g_cos);
    cudaGetSymbolAddress((void**)&Sn, g_sin);
    cudaGetSymbolAddress((void**)&xh, g_xh);
    cudaGetSymbolAddress((void**)&Wqh, g_Wqh);
    cudaGetSymbolAddress((void**)&Wkh, g_Wkh);
    cudaGetSymbolAddress((void**)&Wvh, g_Wvh);
    cudaGetSymbolAddress((void**)&Woh, g_Woh);
    cudaGetSymbolAddress((void**)&Qh, g_Qh);
    cudaGetSymbolAddress((void**)&Kh, g_Kh);
    cudaGetSymbolAddress((void**)&Vh, g_Vh);
    cudaGetSymbolAddress((void**)&Oh, g_Oh);

    cudaFuncSetAttribute(flash_kernel,
                         cudaFuncAttributeMaxDynamicSharedMemorySize,
                         FLASH_SMEM);
    cudaFuncSetAttribute(gemm_mma,
                         cudaFuncAttributeMaxDynamicSharedMemorySize,
                         GEMM_SMEM);
    cudaFuncSetAttribute(gemm_mma64,
                         cudaFuncAttributeMaxDynamicSharedMemorySize,
                         GEMM64_SMEM);

    rope_table_kernel<<<(S_LEN * C_HALF + 255) / 256, 256>>>(fa, Cp, Sn);

    int nx4 = S_LEN * DIM_ / 4, nw4 = DIM_ * DIM_ / 4;
    cvt5_kernel<<<dim3((nx4 + 255) / 256, 5), 256>>>(x, Wq, Wk, Wv, Wo,
                                                     xh, Wqh, Wkh, Wvh, Woh,
                                                     nx4, nw4);

    // batched QKV projections: z=0 -> Q(f32), z=1 -> K(f32), z=2 -> V(half)
    dim3 gQKV(DIM_ / 128, S_LEN / 128, 3);
    gemm_mma<<<gQKV, 256, GEMM_SMEM>>>(xh, Wqh, Wkh, Wvh, bq, bk, bv,
                                       Qp, Kp, Vh);

    // RMSNorm + RoPE -> half Q (pre-scaled) and K, one launch
    rms_rope_kernel<<<dim3(S_LEN, 2), 256>>>(Qp, Kp, Qh, Kh, gq, gk, Cp, Sn,
                                             0.08838834764831845f);

    // fused attention: Q-tile 64, 4 warps, 3 CTAs/SM
    dim3 gFlash(S_LEN / 64, NH);
    flash_kernel<<<gFlash, 128, FLASH_SMEM>>>(Qh, Kh, Vh, Oh);

    // out = O @ Wo^T + bo (fp32), M-tile 64 for better makespan
    dim3 gO(DIM_ / 128, S_LEN / 64);
    gemm_mma64<<<gO, 256, GEMM64_SMEM>>>(Oh, Woh, bo, out);
}

// round 16
// speedup vs baseline: 1.0417x; 1.0417x over previous
#include <cuda_runtime.h>
#include <cuda_fp16.h>
#include <math.h>
#include <stdint.h>

#define S_LEN  3072
#define DIM_   2048
#define NH     16
#define HD     128
#define C_HALF 64
#define GF 8
#define GH 16
#define GW 24
#define CF 22
#define CH 21
#define LDK 136   // flash smem leading dim (128 + 8 pad)

// ---------------- scratch ----------------------------------------------------
__device__ float  g_Q[(size_t)S_LEN * DIM_];
__device__ float  g_K[(size_t)S_LEN * DIM_];
__device__ __half g_xh[(size_t)S_LEN * DIM_];
__device__ __half g_Wqh[(size_t)DIM_ * DIM_];
__device__ __half g_Wkh[(size_t)DIM_ * DIM_];
__device__ __half g_Wvh[(size_t)DIM_ * DIM_];
__device__ __half g_Woh[(size_t)DIM_ * DIM_];
__device__ __half g_Qh[(size_t)S_LEN * DIM_];
__device__ __half g_Kh[(size_t)S_LEN * DIM_];
__device__ __half g_Vh[(size_t)S_LEN * DIM_];
__device__ __half g_Oh[(size_t)S_LEN * DIM_];
__device__ float  g_cos[S_LEN * C_HALF];
__device__ float  g_sin[S_LEN * C_HALF];

// ---------------- small kernels ----------------------------------------------
__global__ void cvt5_kernel(const float* __restrict__ X,
                            const float* __restrict__ W0, const float* __restrict__ W1,
                            const float* __restrict__ W2, const float* __restrict__ W3,
                            __half* __restrict__ OX,
                            __half* __restrict__ O0, __half* __restrict__ O1,
                            __half* __restrict__ O2, __half* __restrict__ O3,
                            int nx4, int nw4) {
    int i = blockIdx.x * blockDim.x + threadIdx.x;
    int z = blockIdx.y;
    const float* in;
    __half* out;
    int n;
    if (z == 0)      { in = X;  out = OX; n = nx4; }
    else if (z == 1) { in = W0; out = O0; n = nw4; }
    else if (z == 2) { in = W1; out = O1; n = nw4; }
    else if (z == 3) { in = W2; out = O2; n = nw4; }
    else             { in = W3; out = O3; n = nw4; }
    if (i >= n) return;
    float4 v = ((const float4*)in)[i];
    ((half2*)out)[2 * i]     = __floats2half2_rn(v.x, v.y);
    ((half2*)out)[2 * i + 1] = __floats2half2_rn(v.z, v.w);
}

__global__ void rope_table_kernel(const float* __restrict__ fa,
                                  float* __restrict__ ctab,
                                  float* __restrict__ stab) {
    int idx = blockIdx.x * blockDim.x + threadIdx.x;
    if (idx >= S_LEN * C_HALF) return;
    int s = idx >> 6;
    int j = idx & 63;
    int f = s / (GH * GW);
    int h = (s / GW) % GH;
    int w = s % GW;
    int row = (j < CF) ? f : (j < CF + CH) ? h : w;
    float a = fa[row * C_HALF + j];
    ctab[idx] = cosf(a);
    stab[idx] = sinf(a);
}

// grid (S_LEN, 2): z=0 -> Q (scaled), z=1 -> K
__global__ void rms_rope_kernel(const float* __restrict__ inQ,
                                const float* __restrict__ inK,
                                __half* __restrict__ outQ,
                                __half* __restrict__ outK,
                                const float* __restrict__ gq,
                                const float* __restrict__ gk,
                                const float* __restrict__ ctab,
                                const float* __restrict__ stab,
                                float scaleQ) {
    int s = blockIdx.x;
    int z = blockIdx.y;
    const float* row = ((z == 0) ? inQ : inK) + (size_t)s * DIM_;
    half2* orow = (half2*)(((z == 0) ? outQ : outK) + (size_t)s * DIM_);
    const float* g = (z == 0) ? gq : gk;
    float scale = (z == 0) ? scaleQ : 1.0f;
    int tid = threadIdx.x;

    float ss = 0.f;
    #pragma unroll
    for (int i = tid; i < DIM_; i += 256) {
        float v = row[i];
        ss += v * v;
    }
    __shared__ float red[256];
    red[tid] = ss;
    __syncthreads();
    #pragma unroll
    for (int off = 128; off > 0; off >>= 1) {
        if (tid < off) red[tid] += red[tid + off];
        __syncthreads();
    }
    float inv = rsqrtf(red[0] * (1.0f / DIM_) + 1e-6f) * scale;

    const float* crow = ctab + s * C_HALF;
    const float* srow = stab + s * C_HALF;
    #pragma unroll
    for (int p = tid; p < DIM_ / 2; p += 256) {
        int j = p & (C_HALF - 1);
        float c = crow[j], sn = srow[j];
        float te = row[2 * p]     * inv * g[2 * p];
        float to = row[2 * p + 1] * inv * g[2 * p + 1];
        orow[p] = __floats2half2_rn(te * c - to * sn, te * sn + to * c);
    }
}

// ---------------- cp.async / mma helpers -------------------------------------
__device__ __forceinline__ void cp_async16(void* smem, const void* gmem) {
    unsigned s = (unsigned)__cvta_generic_to_shared(smem);
    asm volatile("cp.async.cg.shared.global [%0], [%1], 16;\n"
                 :: "r"(s), "l"(gmem));
}
__device__ __forceinline__ void cp_commit() {
    asm volatile("cp.async.commit_group;\n");
}
template <int N>
__device__ __forceinline__ void cp_wait() {
    asm volatile("cp.async.wait_group %0;\n" :: "n"(N));
}

__device__ __forceinline__ void mma16816(float* c, const unsigned* a,
                                         const unsigned* b) {
    asm volatile("mma.sync.aligned.m16n8k16.row.col.f32.f16.f16.f32 "
                 "{%0,%1,%2,%3}, {%4,%5,%6,%7}, {%8,%9}, {%0,%1,%2,%3};\n"
                 : "+f"(c[0]), "+f"(c[1]), "+f"(c[2]), "+f"(c[3])
                 : "r"(a[0]), "r"(a[1]), "r"(a[2]), "r"(a[3]),
                   "r"(b[0]), "r"(b[1]));
}
__device__ __forceinline__ void ldsm_x4(unsigned* r, unsigned a) {
    asm volatile("ldmatrix.sync.aligned.m8n8.x4.shared.b16 {%0,%1,%2,%3}, [%4];\n"
                 : "=r"(r[0]), "=r"(r[1]), "=r"(r[2]), "=r"(r[3]) : "r"(a));
}
__device__ __forceinline__ void ldsm_x2(unsigned* r, unsigned a) {
    asm volatile("ldmatrix.sync.aligned.m8n8.x2.shared.b16 {%0,%1}, [%2];\n"
                 : "=r"(r[0]), "=r"(r[1]) : "r"(a));
}
__device__ __forceinline__ void ldsm_x2t(unsigned* r, unsigned a) {
    asm volatile("ldmatrix.sync.aligned.m8n8.x2.trans.shared.b16 {%0,%1}, [%2];\n"
                 : "=r"(r[0]), "=r"(r[1]) : "r"(a));
}
__device__ __forceinline__ unsigned packh2(float a, float b) {
    half2 h = __floats2half2_rn(a, b);
    return *(unsigned*)&h;
}

// ---------------- mma.sync GEMM NT (round-8 proven: 3-stage, bottom barrier) -
#define GSTG 3
#define GLD 40
#define GSLOT (2 * 128 * GLD)
#define GEMM_SMEM (GSTG * GSLOT * 2)  // 61440 bytes

__global__ __launch_bounds__(256, 2)
void gemm_mma(const __half* __restrict__ A,
              const __half* __restrict__ B0, const __half* __restrict__ B1,
              const __half* __restrict__ B2,
              const float* __restrict__ bias0, const float* __restrict__ bias1,
              const float* __restrict__ bias2,
              float* __restrict__ Cf0, float* __restrict__ Cf1,
              __half* __restrict__ Ch2) {
    extern __shared__ __half gsm[];
    int z = blockIdx.z;
    const __half* Bw = (z == 0) ? B0 : (z == 1) ? B1 : B2;
    const float* bias = (z == 0) ? bias0 : (z == 1) ? bias1 : bias2;

    int m0 = blockIdx.y * 128, n0 = blockIdx.x * 128;
    int tid = threadIdx.x;
    int w = tid >> 5, lane = tid & 31;
    int wm = w & 3, wn = w >> 2;

    int lr = tid >> 2, lc = (tid & 3) << 3;
    const __half* gA = A + (size_t)(m0 + lr) * DIM_ + lc;
    const __half* gB = Bw + (size_t)(n0 + lr) * DIM_ + lc;
    unsigned sbase = (unsigned)__cvta_generic_to_shared(gsm);

    int a_r = (lane & 7) + (lane & 8);
    int a_c = (lane & 16) >> 1;
    int b_r = (lane & 7) + (((lane >> 4) & 1) << 3);
    int b_c = ((lane >> 3) & 1) << 3;

    float cacc[2][8][4];
    #pragma unroll
    for (int i = 0; i < 2; ++i)
        #pragma unroll
        for (int f = 0; f < 8; ++f)
            cacc[i][f][0] = cacc[i][f][1] = cacc[i][f][2] = cacc[i][f][3] = 0.f;

    const int nk = DIM_ / 32;   // 64

    #pragma unroll
    for (int c = 0; c < 2; ++c) {
        __half* sA = gsm + c * GSLOT;
        __half* sB = sA + 128 * GLD;
        int kofs = c * 32;
        cp_async16(sA + lr * GLD + lc, gA + kofs);
        cp_async16(sA + (lr + 64) * GLD + lc, gA + kofs + (size_t)64 * DIM_);
        cp_async16(sB + lr * GLD + lc, gB + kofs);
        cp_async16(sB + (lr + 64) * GLD + lc, gB + kofs + (size_t)64 * DIM_);
        cp_commit();
    }

    for (int it = 0; it < nk; ++it) {
        if (it + 1 < nk) cp_wait<1>(); else cp_wait<0>();
        __syncthreads();

        if (it + 2 < nk) {
            int sl = (it + 2) % GSTG;
            __half* sA = gsm + sl * GSLOT;
            __half* sB = sA + 128 * GLD;
            int kofs = (it + 2) * 32;
            cp_async16(sA + lr * GLD + lc, gA + kofs);
            cp_async16(sA + (lr + 64) * GLD + lc, gA + kofs + (size_t)64 * DIM_);
            cp_async16(sB + lr * GLD + lc, gB + kofs);
            cp_async16(sB + (lr + 64) * GLD + lc, gB + kofs + (size_t)64 * DIM_);
            cp_commit();
        }

        unsigned abase = sbase + (unsigned)((it % GSTG) * GSLOT) * 2;
        unsigned bbase = abase + 128 * GLD * 2;
        #pragma unroll
        for (int kb = 0; kb < 32; kb += 16) {
            unsigned af[2][4];
            #pragma unroll
            for (int i = 0; i < 2; ++i)
                ldsm_x4(af[i], abase +
                    (unsigned)(((wm * 32 + i * 16 + a_r) * GLD) + kb + a_c) * 2);
            #pragma unroll
            for (int jj = 0; jj < 4; ++jj) {
                unsigned bf[4];
                ldsm_x4(bf, bbase +
                    (unsigned)(((wn * 64 + jj * 16 + b_r) * GLD) + kb + b_c) * 2);
                #pragma unroll
                for (int i = 0; i < 2; ++i) {
                    mma16816(cacc[i][jj * 2],     af[i], &bf[0]);
                    mma16816(cacc[i][jj * 2 + 1], af[i], &bf[2]);
                }
            }
        }
        __syncthreads();
    }

    int g = lane >> 2, qp = lane & 3;
    #pragma unroll
    for (int i = 0; i < 2; ++i) {
        int r0 = m0 + wm * 32 + i * 16 + g;
        #pragma unroll
        for (int f = 0; f < 8; ++f) {
            int jj = f >> 1, hf = f & 1;
            int col = n0 + wn * 64 + jj * 16 + hf * 8 + qp * 2;
            float b0 = bias[col], b1 = bias[col + 1];
            float* cc = cacc[i][f];
            if (z == 2) {
                *(half2*)&Ch2[(size_t)r0 * DIM_ + col] =
                    __floats2half2_rn(cc[0] + b0, cc[1] + b1);
                *(half2*)&Ch2[(size_t)(r0 + 8) * DIM_ + col] =
                    __floats2half2_rn(cc[2] + b0, cc[3] + b1);
            } else {
                float* Cf = (z == 0) ? Cf0 : Cf1;
                float2 v0 = {cc[0] + b0, cc[1] + b1};
                float2 v1 = {cc[2] + b0, cc[3] + b1};
                *(float2*)&Cf[(size_t)r0 * DIM_ + col] = v0;
                *(float2*)&Cf[(size_t)(r0 + 8) * DIM_ + col] = v1;
            }
        }
    }
}

// ---------------- GEMM NT, M-tile 64 (out-proj makespan experiment) ----------
#define G64SLOT ((64 + 128) * GLD)
#define GEMM64_SMEM (GSTG * G64SLOT * 2)  // 46080 bytes

__global__ __launch_bounds__(256, 2)
void gemm_mma64(const __half* __restrict__ A, const __half* __restrict__ B,
                const float* __restrict__ bias, float* __restrict__ C) {
    extern __shared__ __half gsm[];
    int m0 = blockIdx.y * 64, n0 = blockIdx.x * 128;
    int tid = threadIdx.x;
    int w = tid >> 5, lane = tid & 31;
    int wm = w & 3, wn = w >> 2;

    int lr = tid >> 2, lc = (tid & 3) << 3;
    const __half* gA = A + (size_t)(m0 + lr) * DIM_ + lc;
    const __half* gB = B + (size_t)(n0 + lr) * DIM_ + lc;
    unsigned sbase = (unsigned)__cvta_generic_to_shared(gsm);

    int a_r = (lane & 7) + (lane & 8);
    int a_c = (lane & 16) >> 1;
    int b_r = (lane & 7) + (((lane >> 4) & 1) << 3);
    int b_c = ((lane >> 3) & 1) << 3;

    float cacc[8][4];
    #pragma unroll
    for (int f = 0; f < 8; ++f)
        cacc[f][0] = cacc[f][1] = cacc[f][2] = cacc[f][3] = 0.f;

    const int nk = DIM_ / 32;   // 64

    #pragma unroll
    for (int c = 0; c < 2; ++c) {
        __half* sA = gsm + c * G64SLOT;
        __half* sB = sA + 64 * GLD;
        int kofs = c * 32;
        cp_async16(sA + lr * GLD + lc, gA + kofs);
        cp_async16(sB + lr * GLD + lc, gB + kofs);
        cp_async16(sB + (lr + 64) * GLD + lc, gB + kofs + (size_t)64 * DIM_);
        cp_commit();
    }

    for (int it = 0; it < nk; ++it) {
        if (it + 1 < nk) cp_wait<1>(); else cp_wait<0>();
        __syncthreads();

        if (it + 2 < nk) {
            int sl = (it + 2) % GSTG;
            __half* sA = gsm + sl * G64SLOT;
            __half* sB = sA + 64 * GLD;
            int kofs = (it + 2) * 32;
            cp_async16(sA + lr * GLD + lc, gA + kofs);
            cp_async16(sB + lr * GLD + lc, gB + kofs);
            cp_async16(sB + (lr + 64) * GLD + lc, gB + kofs + (size_t)64 * DIM_);
            cp_commit();
        }

        unsigned abase = sbase + (unsigned)((it % GSTG) * G64SLOT) * 2;
        unsigned bbase = abase + 64 * GLD * 2;
        #pragma unroll
        for (int kb = 0; kb < 32; kb += 16) {
            unsigned af[4];
            ldsm_x4(af, abase +
                (unsigned)(((wm * 16 + a_r) * GLD) + kb + a_c) * 2);
            #pragma unroll
            for (int jj = 0; jj < 4; ++jj) {
                unsigned bf[4];
                ldsm_x4(bf, bbase +
                    (unsigned)(((wn * 64 + jj * 16 + b_r) * GLD) + kb + b_c) * 2);
                mma16816(cacc[jj * 2],     af, &bf[0]);
                mma16816(cacc[jj * 2 + 1], af, &bf[2]);
            }
        }
        __syncthreads();
    }

    int g = lane >> 2, qp = lane & 3;
    int r0 = m0 + wm * 16 + g;
    #pragma unroll
    for (int f = 0; f < 8; ++f) {
        int jj = f >> 1, hf = f & 1;
        int col = n0 + wn * 64 + jj * 16 + hf * 8 + qp * 2;
        float b0 = bias[col], b1 = bias[col + 1];
        float* cc = cacc[f];
        float2 v0 = {cc[0] + b0, cc[1] + b1};
        float2 v1 = {cc[2] + b0, cc[3] + b1};
        *(float2*)&C[(size_t)r0 * DIM_ + col] = v0;
        *(float2*)&C[(size_t)(r0 + 8) * DIM_ + col] = v1;
    }
}

// ---------------- flash attention kernel (round-7 proven version) ------------
#define FLASH_SMEM (4 * 64 * LDK * 2)

__global__ __launch_bounds__(256, 1)
void flash_kernel(const __half* __restrict__ Q, const __half* __restrict__ K,
                  const __half* __restrict__ V, __half* __restrict__ O) {
    extern __shared__ __half sm[];
    __half* sK = sm;
    __half* sV = sm + 2 * 64 * LDK;

    int q0 = blockIdx.x * 128;
    int h  = blockIdx.y;
    int tid = threadIdx.x;
    int w = tid >> 5, lane = tid & 31;
    int g = lane >> 2, qp = lane & 3;
    int wm0 = w * 16;

    const __half* Qg = Q + (size_t)q0 * DIM_ + h * HD;
    const __half* Kg = K + h * HD;
    const __half* Vg = V + h * HD;

    #pragma unroll
    for (int it = 0; it < 8; ++it) {
        int slot = tid + it * 256;
        int r = slot >> 4, c = (slot & 15) << 3;
        cp_async16(&sK[r * LDK + c], Qg + (size_t)r * DIM_ + c);
    }
    cp_commit();
    cp_wait<0>();
    __syncthreads();

    unsigned qf[8][4];
    {
        unsigned base = (unsigned)__cvta_generic_to_shared(sK);
        int row = wm0 + (lane & 7) + (lane & 8);
        #pragma unroll
        for (int kk = 0; kk < 8; ++kk) {
            int col = kk * 16 + ((lane & 16) >> 1);
            ldsm_x4(qf[kk], base + (row * LDK + col) * 2);
        }
    }
    __syncthreads();

    float oacc[16][4];
    #pragma unroll
    for (int t = 0; t < 16; ++t)
        #pragma unroll
        for (int c = 0; c < 4; ++c) oacc[t][c] = 0.f;
    float mA = -1e30f, mB = -1e30f, lA = 0.f, lB = 0.f;

    #pragma unroll
    for (int it = 0; it < 4; ++it) {
        int slot = tid + it * 256;
        int r = slot >> 4, c = (slot & 15) << 3;
        cp_async16(&sK[r * LDK + c], Kg + (size_t)r * DIM_ + c);
        cp_async16(&sV[r * LDK + c], Vg + (size_t)r * DIM_ + c);
    }
    cp_commit();

    const int NCH = S_LEN / 64;
    for (int i = 0; i < NCH; ++i) {
        cp_wait<0>();
        __syncthreads();

        if (i + 1 < NCH) {
            int st = (i + 1) & 1;
            const __half* kg = Kg + (size_t)(i + 1) * 64 * DIM_;
            const __half* vg = Vg + (size_t)(i + 1) * 64 * DIM_;
            __half* dK = sK + st * 64 * LDK;
            __half* dV = sV + st * 64 * LDK;
            #pragma unroll
            for (int it = 0; it < 4; ++it) {
                int slot = tid + it * 256;
                int r = slot >> 4, c = (slot & 15) << 3;
                cp_async16(&dK[r * LDK + c], kg + (size_t)r * DIM_ + c);
                cp_async16(&dV[r * LDK + c], vg + (size_t)r * DIM_ + c);
            }
            cp_commit();
        }

        int st = i & 1;
        unsigned kbase = (unsigned)__cvta_generic_to_shared(sK + st * 64 * LDK);
        unsigned vbase = (unsigned)__cvta_generic_to_shared(sV + st * 64 * LDK);

        float sacc[8][4];
        #pragma unroll
        for (int j = 0; j < 8; ++j)
            sacc[j][0] = sacc[j][1] = sacc[j][2] = sacc[j][3] = 0.f;
        #pragma unroll
        for (int j = 0; j < 8; ++j) {
            int krow = 8 * j + (lane & 7);
            #pragma unroll
            for (int kk = 0; kk < 8; ++kk) {
                unsigned b[2];
                int kcol = 16 * kk + (lane & 8);
                ldsm_x2(b, kbase + (krow * LDK + kcol) * 2);
                mma16816(sacc[j], qf[kk], b);
            }
        }

        float cmA = -1e30f, cmB = -1e30f;
        #pragma unroll
        for (int j = 0; j < 8; ++j) {
            cmA = fmaxf(cmA, fmaxf(sacc[j][0], sacc[j][1]));
            cmB = fmaxf(cmB, fmaxf(sacc[j][2], sacc[j][3]));
        }
        cmA = fmaxf(cmA, __shfl_xor_sync(0xffffffffu, cmA, 1));
        cmA = fmaxf(cmA, __shfl_xor_sync(0xffffffffu, cmA, 2));
        cmB = fmaxf(cmB, __shfl_xor_sync(0xffffffffu, cmB, 1));
        cmB = fmaxf(cmB, __shfl_xor_sync(0xffffffffu, cmB, 2));
        float mAn = fmaxf(mA, cmA), mBn = fmaxf(mB, cmB);
        float fA = __expf(mA - mAn), fB = __expf(mB - mBn);

        float sumA = 0.f, sumB = 0.f;
        #pragma unroll
        for (int j = 0; j < 8; ++j) {
            sacc[j][0] = __expf(sacc[j][0] - mAn);
            sacc[j][1] = __expf(sacc[j][1] - mAn);
            sacc[j][2] = __expf(sacc[j][2] - mBn);
            sacc[j][3] = __expf(sacc[j][3] - mBn);
            sumA += sacc[j][0] + sacc[j][1];
            sumB += sacc[j][2] + sacc[j][3];
        }
        sumA += __shfl_xor_sync(0xffffffffu, sumA, 1);
        sumA += __shfl_xor_sync(0xffffffffu, sumA, 2);
        sumB += __shfl_xor_sync(0xffffffffu, sumB, 1);
        sumB += __shfl_xor_sync(0xffffffffu, sumB, 2);
        lA = lA * fA + sumA;
        lB = lB * fB + sumB;
        mA = mAn; mB = mBn;

        #pragma unroll
        for (int t = 0; t < 16; ++t) {
            oacc[t][0] *= fA; oacc[t][1] *= fA;
            oacc[t][2] *= fB; oacc[t][3] *= fB;
        }

        unsigned pf[4][4];
        #pragma unroll
        for (int kt = 0; kt < 4; ++kt) {
            pf[kt][0] = packh2(sacc[2 * kt][0],     sacc[2 * kt][1]);
            pf[kt][1] = packh2(sacc[2 * kt][2],     sacc[2 * kt][3]);
            pf[kt][2] = packh2(sacc[2 * kt + 1][0], sacc[2 * kt + 1][1]);
            pf[kt][3] = packh2(sacc[2 * kt + 1][2], sacc[2 * kt + 1][3]);
        }

        #pragma unroll
        for (int t = 0; t < 16; ++t) {
            #pragma unroll
            for (int kt = 0; kt < 4; ++kt) {
                unsigned b[2];
                int vrow = 16 * kt + (lane & 15);
                ldsm_x2t(b, vbase + (vrow * LDK + 8 * t) * 2);
                mma16816(oacc[t], pf[kt], b);
            }
        }
    }

    float invA = 1.f / lA, invB = 1.f / lB;
    size_t b0 = (size_t)(q0 + wm0 + g) * DIM_ + h * HD + qp * 2;
    size_t b1 = b0 + (size_t)8 * DIM_;
    #pragma unroll
    for (int t = 0; t < 16; ++t) {
        *(half2*)&O[b0 + 8 * t] =
            __floats2half2_rn(oacc[t][0] * invA, oacc[t][1] * invA);
        *(half2*)&O[b1 + 8 * t] =
            __floats2half2_rn(oacc[t][2] * invB, oacc[t][3] * invB);
    }
}

// ---------------- launch ------------------------------------------------------
extern "C" void kernel_launch(void* const* d_in, const int* in_sizes, int n_in,
                              void* d_out, int out_size) {
    const float* x   = (const float*)d_in[0];
    const float* fa  = (const float*)d_in[1];
    const float* Wq  = (const float*)d_in[2];
    const float* bq  = (const float*)d_in[3];
    const float* Wk  = (const float*)d_in[4];
    const float* bk  = (const float*)d_in[5];
    const float* Wv  = (const float*)d_in[6];
    const float* bv  = (const float*)d_in[7];
    const float* Wo  = (const float*)d_in[8];
    const float* bo  = (const float*)d_in[9];
    const float* gq  = (const float*)d_in[10];
    const float* gk  = (const float*)d_in[11];
    float* out = (float*)d_out;

    float *Qp, *Kp, *Cp, *Sn;
    __half *xh, *Wqh, *Wkh, *Wvh, *Woh, *Qh, *Kh, *Vh, *Oh;
    cudaGetSymbolAddress((void**)&Qp, g_Q);
    cudaGetSymbolAddress((void**)&Kp, g_K);
    cudaGetSymbolAddress((void**)&Cp, g_cos);
    cudaGetSymbolAddress((void**)&Sn, g_sin);
    cudaGetSymbolAddress((void**)&xh, g_xh);
    cudaGetSymbolAddress((void**)&Wqh, g_Wqh);
    cudaGetSymbolAddress((void**)&Wkh, g_Wkh);
    cudaGetSymbolAddress((void**)&Wvh, g_Wvh);
    cudaGetSymbolAddress((void**)&Woh, g_Woh);
    cudaGetSymbolAddress((void**)&Qh, g_Qh);
    cudaGetSymbolAddress((void**)&Kh, g_Kh);
    cudaGetSymbolAddress((void**)&Vh, g_Vh);
    cudaGetSymbolAddress((void**)&Oh, g_Oh);

    cudaFuncSetAttribute(flash_kernel,
                         cudaFuncAttributeMaxDynamicSharedMemorySize,
                         FLASH_SMEM);
    cudaFuncSetAttribute(gemm_mma,
                         cudaFuncAttributeMaxDynamicSharedMemorySize,
                         GEMM_SMEM);
    cudaFuncSetAttribute(gemm_mma64,
                         cudaFuncAttributeMaxDynamicSharedMemorySize,
                         GEMM64_SMEM);

    rope_table_kernel<<<(S_LEN * C_HALF + 255) / 256, 256>>>(fa, Cp, Sn);

    int nx4 = S_LEN * DIM_ / 4, nw4 = DIM_ * DIM_ / 4;
    cvt5_kernel<<<dim3((nx4 + 255) / 256, 5), 256>>>(x, Wq, Wk, Wv, Wo,
                                                     xh, Wqh, Wkh, Wvh, Woh,
                                                     nx4, nw4);

    // batched QKV projections: z=0 -> Q(f32), z=1 -> K(f32), z=2 -> V(half)
    dim3 gQKV(DIM_ / 128, S_LEN / 128, 3);
    gemm_mma<<<gQKV, 256, GEMM_SMEM>>>(xh, Wqh, Wkh, Wvh, bq, bk, bv,
                                       Qp, Kp, Vh);

    // RMSNorm + RoPE -> half Q (pre-scaled) and K, one launch
    rms_rope_kernel<<<dim3(S_LEN, 2), 256>>>(Qp, Kp, Qh, Kh, gq, gk, Cp, Sn,
                                             0.08838834764831845f);

    // fused attention (proven 256-thread, Q-tile 128)
    dim3 gFlash(S_LEN / 128, NH);
    flash_kernel<<<gFlash, 256, FLASH_SMEM>>>(Qh, Kh, Vh, Oh);

    // out = O @ Wo^T + bo (fp32), M-tile 64 makespan experiment
    dim3 gO(DIM_ / 128, S_LEN / 64);
    gemm_mma64<<<gO, 256, GEMM64_SMEM>>>(Oh, Woh, bo, out);
}

// round 17
// speedup vs baseline: 1.0778x; 1.0346x over previous
#include <cuda_runtime.h>
#include <cuda_fp16.h>
#include <math.h>
#include <stdint.h>

#define S_LEN  3072
#define DIM_   2048
#define NH     16
#define HD     128
#define C_HALF 64
#define GF 8
#define GH 16
#define GW 24
#define CF 22
#define CH 21
#define LDK 136   // flash smem leading dim (128 + 8 pad)

// ---------------- scratch ----------------------------------------------------
__device__ __half g_xh[(size_t)S_LEN * DIM_];
__device__ __half g_Wqh[(size_t)DIM_ * DIM_];
__device__ __half g_Wkh[(size_t)DIM_ * DIM_];
__device__ __half g_Wvh[(size_t)DIM_ * DIM_];
__device__ __half g_Woh[(size_t)DIM_ * DIM_];
__device__ __half g_Qh[(size_t)S_LEN * DIM_];
__device__ __half g_Kh[(size_t)S_LEN * DIM_];
__device__ __half g_Vh[(size_t)S_LEN * DIM_];
__device__ __half g_Oh[(size_t)S_LEN * DIM_];
__device__ float  g_cos[S_LEN * C_HALF];
__device__ float  g_sin[S_LEN * C_HALF];

// ---------------- small kernels ----------------------------------------------
__global__ void cvt5_kernel(const float* __restrict__ X,
                            const float* __restrict__ W0, const float* __restrict__ W1,
                            const float* __restrict__ W2, const float* __restrict__ W3,
                            __half* __restrict__ OX,
                            __half* __restrict__ O0, __half* __restrict__ O1,
                            __half* __restrict__ O2, __half* __restrict__ O3,
                            int nx4, int nw4) {
    int i = blockIdx.x * blockDim.x + threadIdx.x;
    int z = blockIdx.y;
    const float* in;
    __half* out;
    int n;
    if (z == 0)      { in = X;  out = OX; n = nx4; }
    else if (z == 1) { in = W0; out = O0; n = nw4; }
    else if (z == 2) { in = W1; out = O1; n = nw4; }
    else if (z == 3) { in = W2; out = O2; n = nw4; }
    else             { in = W3; out = O3; n = nw4; }
    if (i >= n) return;
    float4 v = ((const float4*)in)[i];
    ((half2*)out)[2 * i]     = __floats2half2_rn(v.x, v.y);
    ((half2*)out)[2 * i + 1] = __floats2half2_rn(v.z, v.w);
}

__global__ void rope_table_kernel(const float* __restrict__ fa,
                                  float* __restrict__ ctab,
                                  float* __restrict__ stab) {
    int idx = blockIdx.x * blockDim.x + threadIdx.x;
    if (idx >= S_LEN * C_HALF) return;
    int s = idx >> 6;
    int j = idx & 63;
    int f = s / (GH * GW);
    int h = (s / GW) % GH;
    int w = s % GW;
    int row = (j < CF) ? f : (j < CF + CH) ? h : w;
    float a = fa[row * C_HALF + j];
    ctab[idx] = cosf(a);
    stab[idx] = sinf(a);
}

// grid (S_LEN, 2): z=0 -> Q (scaled), z=1 -> K. IN-PLACE on half buffers.
// Safe: sum phase reads all half2 slots before the reduction barrier; write
// phase re-reads and overwrites only this thread's own half2 slots.
__global__ void rms_rope_kernel(__half* __restrict__ bufQ,
                                __half* __restrict__ bufK,
                                const float* __restrict__ gq,
                                const float* __restrict__ gk,
                                const float* __restrict__ ctab,
                                const float* __restrict__ stab,
                                float scaleQ) {
    int s = blockIdx.x;
    int z = blockIdx.y;
    half2* row = (half2*)(((z == 0) ? bufQ : bufK) + (size_t)s * DIM_);
    const float* g = (z == 0) ? gq : gk;
    float scale = (z == 0) ? scaleQ : 1.0f;
    int tid = threadIdx.x;

    float ss = 0.f;
    #pragma unroll
    for (int p = tid; p < DIM_ / 2; p += 256) {
        float2 v = __half22float2(row[p]);
        ss += v.x * v.x + v.y * v.y;
    }
    __shared__ float red[256];
    red[tid] = ss;
    __syncthreads();
    #pragma unroll
    for (int off = 128; off > 0; off >>= 1) {
        if (tid < off) red[tid] += red[tid + off];
        __syncthreads();
    }
    float inv = rsqrtf(red[0] * (1.0f / DIM_) + 1e-6f) * scale;

    const float* crow = ctab + s * C_HALF;
    const float* srow = stab + s * C_HALF;
    #pragma unroll
    for (int p = tid; p < DIM_ / 2; p += 256) {
        int j = p & (C_HALF - 1);
        float c = crow[j], sn = srow[j];
        float2 t = __half22float2(row[p]);
        float te = t.x * inv * g[2 * p];
        float to = t.y * inv * g[2 * p + 1];
        row[p] = __floats2half2_rn(te * c - to * sn, te * sn + to * c);
    }
}

// ---------------- cp.async / mma helpers -------------------------------------
__device__ __forceinline__ void cp_async16(void* smem, const void* gmem) {
    unsigned s = (unsigned)__cvta_generic_to_shared(smem);
    asm volatile("cp.async.cg.shared.global [%0], [%1], 16;\n"
                 :: "r"(s), "l"(gmem));
}
__device__ __forceinline__ void cp_commit() {
    asm volatile("cp.async.commit_group;\n");
}
template <int N>
__device__ __forceinline__ void cp_wait() {
    asm volatile("cp.async.wait_group %0;\n" :: "n"(N));
}

__device__ __forceinline__ void mma16816(float* c, const unsigned* a,
                                         const unsigned* b) {
    asm volatile("mma.sync.aligned.m16n8k16.row.col.f32.f16.f16.f32 "
                 "{%0,%1,%2,%3}, {%4,%5,%6,%7}, {%8,%9}, {%0,%1,%2,%3};\n"
                 : "+f"(c[0]), "+f"(c[1]), "+f"(c[2]), "+f"(c[3])
                 : "r"(a[0]), "r"(a[1]), "r"(a[2]), "r"(a[3]),
                   "r"(b[0]), "r"(b[1]));
}
__device__ __forceinline__ void ldsm_x4(unsigned* r, unsigned a) {
    asm volatile("ldmatrix.sync.aligned.m8n8.x4.shared.b16 {%0,%1,%2,%3}, [%4];\n"
                 : "=r"(r[0]), "=r"(r[1]), "=r"(r[2]), "=r"(r[3]) : "r"(a));
}
__device__ __forceinline__ void ldsm_x2(unsigned* r, unsigned a) {
    asm volatile("ldmatrix.sync.aligned.m8n8.x2.shared.b16 {%0,%1}, [%2];\n"
                 : "=r"(r[0]), "=r"(r[1]) : "r"(a));
}
__device__ __forceinline__ void ldsm_x2t(unsigned* r, unsigned a) {
    asm volatile("ldmatrix.sync.aligned.m8n8.x2.trans.shared.b16 {%0,%1}, [%2];\n"
                 : "=r"(r[0]), "=r"(r[1]) : "r"(a));
}
__device__ __forceinline__ unsigned packh2(float a, float b) {
    half2 h = __floats2half2_rn(a, b);
    return *(unsigned*)&h;
}

// ---------------- mma.sync GEMM NT (round-8 proven: 3-stage, bottom barrier) -
// Templated output type; otherwise identical to the proven kernel.
#define GSTG 3
#define GLD 40
#define GSLOT (2 * 128 * GLD)
#define GEMM_SMEM (GSTG * GSLOT * 2)  // 61440 bytes

template <typename OutT>
__global__ __launch_bounds__(256, 2)
void gemm_mma(const __half* __restrict__ A,
              const __half* __restrict__ B0, const __half* __restrict__ B1,
              const __half* __restrict__ B2,
              const float* __restrict__ bias0, const float* __restrict__ bias1,
              const float* __restrict__ bias2,
              OutT* __restrict__ C0, OutT* __restrict__ C1,
              OutT* __restrict__ C2) {
    extern __shared__ __half gsm[];
    int z = blockIdx.z;
    const __half* Bw = (z == 0) ? B0 : (z == 1) ? B1 : B2;
    const float* bias = (z == 0) ? bias0 : (z == 1) ? bias1 : bias2;
    OutT* C = (z == 0) ? C0 : (z == 1) ? C1 : C2;

    int m0 = blockIdx.y * 128, n0 = blockIdx.x * 128;
    int tid = threadIdx.x;
    int w = tid >> 5, lane = tid & 31;
    int wm = w & 3, wn = w >> 2;

    int lr = tid >> 2, lc = (tid & 3) << 3;
    const __half* gA = A + (size_t)(m0 + lr) * DIM_ + lc;
    const __half* gB = Bw + (size_t)(n0 + lr) * DIM_ + lc;
    unsigned sbase = (unsigned)__cvta_generic_to_shared(gsm);

    int a_r = (lane & 7) + (lane & 8);
    int a_c = (lane & 16) >> 1;
    int b_r = (lane & 7) + (((lane >> 4) & 1) << 3);
    int b_c = ((lane >> 3) & 1) << 3;

    float cacc[2][8][4];
    #pragma unroll
    for (int i = 0; i < 2; ++i)
        #pragma unroll
        for (int f = 0; f < 8; ++f)
            cacc[i][f][0] = cacc[i][f][1] = cacc[i][f][2] = cacc[i][f][3] = 0.f;

    const int nk = DIM_ / 32;   // 64

    #pragma unroll
    for (int c = 0; c < 2; ++c) {
        __half* sA = gsm + c * GSLOT;
        __half* sB = sA + 128 * GLD;
        int kofs = c * 32;
        cp_async16(sA + lr * GLD + lc, gA + kofs);
        cp_async16(sA + (lr + 64) * GLD + lc, gA + kofs + (size_t)64 * DIM_);
        cp_async16(sB + lr * GLD + lc, gB + kofs);
        cp_async16(sB + (lr + 64) * GLD + lc, gB + kofs + (size_t)64 * DIM_);
        cp_commit();
    }

    for (int it = 0; it < nk; ++it) {
        if (it + 1 < nk) cp_wait<1>(); else cp_wait<0>();
        __syncthreads();

        if (it + 2 < nk) {
            int sl = (it + 2) % GSTG;
            __half* sA = gsm + sl * GSLOT;
            __half* sB = sA + 128 * GLD;
            int kofs = (it + 2) * 32;
            cp_async16(sA + lr * GLD + lc, gA + kofs);
            cp_async16(sA + (lr + 64) * GLD + lc, gA + kofs + (size_t)64 * DIM_);
            cp_async16(sB + lr * GLD + lc, gB + kofs);
            cp_async16(sB + (lr + 64) * GLD + lc, gB + kofs + (size_t)64 * DIM_);
            cp_commit();
        }

        unsigned abase = sbase + (unsigned)((it % GSTG) * GSLOT) * 2;
        unsigned bbase = abase + 128 * GLD * 2;
        #pragma unroll
        for (int kb = 0; kb < 32; kb += 16) {
            unsigned af[2][4];
            #pragma unroll
            for (int i = 0; i < 2; ++i)
                ldsm_x4(af[i], abase +
                    (unsigned)(((wm * 32 + i * 16 + a_r) * GLD) + kb + a_c) * 2);
            #pragma unroll
            for (int jj = 0; jj < 4; ++jj) {
                unsigned bf[4];
                ldsm_x4(bf, bbase +
                    (unsigned)(((wn * 64 + jj * 16 + b_r) * GLD) + kb + b_c) * 2);
                #pragma unroll
                for (int i = 0; i < 2; ++i) {
                    mma16816(cacc[i][jj * 2],     af[i], &bf[0]);
                    mma16816(cacc[i][jj * 2 + 1], af[i], &bf[2]);
                }
            }
        }
        __syncthreads();
    }

    int g = lane >> 2, qp = lane & 3;
    #pragma unroll
    for (int i = 0; i < 2; ++i) {
        int r0 = m0 + wm * 32 + i * 16 + g;
        #pragma unroll
        for (int f = 0; f < 8; ++f) {
            int jj = f >> 1, hf = f & 1;
            int col = n0 + wn * 64 + jj * 16 + hf * 8 + qp * 2;
            float b0 = bias[col], b1 = bias[col + 1];
            float* cc = cacc[i][f];
            if (sizeof(OutT) == 2) {
                __half* Ch = (__half*)C;
                *(half2*)&Ch[(size_t)r0 * DIM_ + col] =
                    __floats2half2_rn(cc[0] + b0, cc[1] + b1);
                *(half2*)&Ch[(size_t)(r0 + 8) * DIM_ + col] =
                    __floats2half2_rn(cc[2] + b0, cc[3] + b1);
            } else {
                float* Cf = (float*)C;
                float2 v0 = {cc[0] + b0, cc[1] + b1};
                float2 v1 = {cc[2] + b0, cc[3] + b1};
                *(float2*)&Cf[(size_t)r0 * DIM_ + col] = v0;
                *(float2*)&Cf[(size_t)(r0 + 8) * DIM_ + col] = v1;
            }
        }
    }
}

// ---------------- flash attention kernel (round-7 proven version) ------------
#define FLASH_SMEM (4 * 64 * LDK * 2)

__global__ __launch_bounds__(256, 1)
void flash_kernel(const __half* __restrict__ Q, const __half* __restrict__ K,
                  const __half* __restrict__ V, __half* __restrict__ O) {
    extern __shared__ __half sm[];
    __half* sK = sm;
    __half* sV = sm + 2 * 64 * LDK;

    int q0 = blockIdx.x * 128;
    int h  = blockIdx.y;
    int tid = threadIdx.x;
    int w = tid >> 5, lane = tid & 31;
    int g = lane >> 2, qp = lane & 3;
    int wm0 = w * 16;

    const __half* Qg = Q + (size_t)q0 * DIM_ + h * HD;
    const __half* Kg = K + h * HD;
    const __half* Vg = V + h * HD;

    #pragma unroll
    for (int it = 0; it < 8; ++it) {
        int slot = tid + it * 256;
        int r = slot >> 4, c = (slot & 15) << 3;
        cp_async16(&sK[r * LDK + c], Qg + (size_t)r * DIM_ + c);
    }
    cp_commit();
    cp_wait<0>();
    __syncthreads();

    unsigned qf[8][4];
    {
        unsigned base = (unsigned)__cvta_generic_to_shared(sK);
        int row = wm0 + (lane & 7) + (lane & 8);
        #pragma unroll
        for (int kk = 0; kk < 8; ++kk) {
            int col = kk * 16 + ((lane & 16) >> 1);
            ldsm_x4(qf[kk], base + (row * LDK + col) * 2);
        }
    }
    __syncthreads();

    float oacc[16][4];
    #pragma unroll
    for (int t = 0; t < 16; ++t)
        #pragma unroll
        for (int c = 0; c < 4; ++c) oacc[t][c] = 0.f;
    float mA = -1e30f, mB = -1e30f, lA = 0.f, lB = 0.f;

    #pragma unroll
    for (int it = 0; it < 4; ++it) {
        int slot = tid + it * 256;
        int r = slot >> 4, c = (slot & 15) << 3;
        cp_async16(&sK[r * LDK + c], Kg + (size_t)r * DIM_ + c);
        cp_async16(&sV[r * LDK + c], Vg + (size_t)r * DIM_ + c);
    }
    cp_commit();

    const int NCH = S_LEN / 64;
    for (int i = 0; i < NCH; ++i) {
        cp_wait<0>();
        __syncthreads();

        if (i + 1 < NCH) {
            int st = (i + 1) & 1;
            const __half* kg = Kg + (size_t)(i + 1) * 64 * DIM_;
            const __half* vg = Vg + (size_t)(i + 1) * 64 * DIM_;
            __half* dK = sK + st * 64 * LDK;
            __half* dV = sV + st * 64 * LDK;
            #pragma unroll
            for (int it = 0; it < 4; ++it) {
                int slot = tid + it * 256;
                int r = slot >> 4, c = (slot & 15) << 3;
                cp_async16(&dK[r * LDK + c], kg + (size_t)r * DIM_ + c);
                cp_async16(&dV[r * LDK + c], vg + (size_t)r * DIM_ + c);
            }
            cp_commit();
        }

        int st = i & 1;
        unsigned kbase = (unsigned)__cvta_generic_to_shared(sK + st * 64 * LDK);
        unsigned vbase = (unsigned)__cvta_generic_to_shared(sV + st * 64 * LDK);

        float sacc[8][4];
        #pragma unroll
        for (int j = 0; j < 8; ++j)
            sacc[j][0] = sacc[j][1] = sacc[j][2] = sacc[j][3] = 0.f;
        #pragma unroll
        for (int j = 0; j < 8; ++j) {
            int krow = 8 * j + (lane & 7);
            #pragma unroll
            for (int kk = 0; kk < 8; ++kk) {
                unsigned b[2];
                int kcol = 16 * kk + (lane & 8);
                ldsm_x2(b, kbase + (krow * LDK + kcol) * 2);
                mma16816(sacc[j], qf[kk], b);
            }
        }

        float cmA = -1e30f, cmB = -1e30f;
        #pragma unroll
        for (int j = 0; j < 8; ++j) {
            cmA = fmaxf(cmA, fmaxf(sacc[j][0], sacc[j][1]));
            cmB = fmaxf(cmB, fmaxf(sacc[j][2], sacc[j][3]));
        }
        cmA = fmaxf(cmA, __shfl_xor_sync(0xffffffffu, cmA, 1));
        cmA = fmaxf(cmA, __shfl_xor_sync(0xffffffffu, cmA, 2));
        cmB = fmaxf(cmB, __shfl_xor_sync(0xffffffffu, cmB, 1));
        cmB = fmaxf(cmB, __shfl_xor_sync(0xffffffffu, cmB, 2));
        float mAn = fmaxf(mA, cmA), mBn = fmaxf(mB, cmB);
        float fA = __expf(mA - mAn), fB = __expf(mB - mBn);

        float sumA = 0.f, sumB = 0.f;
        #pragma unroll
        for (int j = 0; j < 8; ++j) {
            sacc[j][0] = __expf(sacc[j][0] - mAn);
            sacc[j][1] = __expf(sacc[j][1] - mAn);
            sacc[j][2] = __expf(sacc[j][2] - mBn);
            sacc[j][3] = __expf(sacc[j][3] - mBn);
            sumA += sacc[j][0] + sacc[j][1];
            sumB += sacc[j][2] + sacc[j][3];
        }
        sumA += __shfl_xor_sync(0xffffffffu, sumA, 1);
        sumA += __shfl_xor_sync(0xffffffffu, sumA, 2);
        sumB += __shfl_xor_sync(0xffffffffu, sumB, 1);
        sumB += __shfl_xor_sync(0xffffffffu, sumB, 2);
        lA = lA * fA + sumA;
        lB = lB * fB + sumB;
        mA = mAn; mB = mBn;

        #pragma unroll
        for (int t = 0; t < 16; ++t) {
            oacc[t][0] *= fA; oacc[t][1] *= fA;
            oacc[t][2] *= fB; oacc[t][3] *= fB;
        }

        unsigned pf[4][4];
        #pragma unroll
        for (int kt = 0; kt < 4; ++kt) {
            pf[kt][0] = packh2(sacc[2 * kt][0],     sacc[2 * kt][1]);
            pf[kt][1] = packh2(sacc[2 * kt][2],     sacc[2 * kt][3]);
            pf[kt][2] = packh2(sacc[2 * kt + 1][0], sacc[2 * kt + 1][1]);
            pf[kt][3] = packh2(sacc[2 * kt + 1][2], sacc[2 * kt + 1][3]);
        }

        #pragma unroll
        for (int t = 0; t < 16; ++t) {
            #pragma unroll
            for (int kt = 0; kt < 4; ++kt) {
                unsigned b[2];
                int vrow = 16 * kt + (lane & 15);
                ldsm_x2t(b, vbase + (vrow * LDK + 8 * t) * 2);
                mma16816(oacc[t], pf[kt], b);
            }
        }
    }

    float invA = 1.f / lA, invB = 1.f / lB;
    size_t b0 = (size_t)(q0 + wm0 + g) * DIM_ + h * HD + qp * 2;
    size_t b1 = b0 + (size_t)8 * DIM_;
    #pragma unroll
    for (int t = 0; t < 16; ++t) {
        *(half2*)&O[b0 + 8 * t] =
            __floats2half2_rn(oacc[t][0] * invA, oacc[t][1] * invA);
        *(half2*)&O[b1 + 8 * t] =
            __floats2half2_rn(oacc[t][2] * invB, oacc[t][3] * invB);
    }
}

// ---------------- launch ------------------------------------------------------
extern "C" void kernel_launch(void* const* d_in, const int* in_sizes, int n_in,
                              void* d_out, int out_size) {
    const float* x   = (const float*)d_in[0];
    const float* fa  = (const float*)d_in[1];
    const float* Wq  = (const float*)d_in[2];
    const float* bq  = (const float*)d_in[3];
    const float* Wk  = (const float*)d_in[4];
    const float* bk  = (const float*)d_in[5];
    const float* Wv  = (const float*)d_in[6];
    const float* bv  = (const float*)d_in[7];
    const float* Wo  = (const float*)d_in[8];
    const float* bo  = (const float*)d_in[9];
    const float* gq  = (const float*)d_in[10];
    const float* gk  = (const float*)d_in[11];
    float* out = (float*)d_out;

    float *Cp, *Sn;
    __half *xh, *Wqh, *Wkh, *Wvh, *Woh, *Qh, *Kh, *Vh, *Oh;
    cudaGetSymbolAddress((void**)&Cp, g_cos);
    cudaGetSymbolAddress((void**)&Sn, g_sin);
    cudaGetSymbolAddress((void**)&xh, g_xh);
    cudaGetSymbolAddress((void**)&Wqh, g_Wqh);
    cudaGetSymbolAddress((void**)&Wkh, g_Wkh);
    cudaGetSymbolAddress((void**)&Wvh, g_Wvh);
    cudaGetSymbolAddress((void**)&Woh, g_Woh);
    cudaGetSymbolAddress((void**)&Qh, g_Qh);
    cudaGetSymbolAddress((void**)&Kh, g_Kh);
    cudaGetSymbolAddress((void**)&Vh, g_Vh);
    cudaGetSymbolAddress((void**)&Oh, g_Oh);

    cudaFuncSetAttribute(flash_kernel,
                         cudaFuncAttributeMaxDynamicSharedMemorySize,
                         FLASH_SMEM);
    cudaFuncSetAttribute(gemm_mma<__half>,
                         cudaFuncAttributeMaxDynamicSharedMemorySize,
                         GEMM_SMEM);
    cudaFuncSetAttribute(gemm_mma<float>,
                         cudaFuncAttributeMaxDynamicSharedMemorySize,
                         GEMM_SMEM);

    rope_table_kernel<<<(S_LEN * C_HALF + 255) / 256, 256>>>(fa, Cp, Sn);

    int nx4 = S_LEN * DIM_ / 4, nw4 = DIM_ * DIM_ / 4;
    cvt5_kernel<<<dim3((nx4 + 255) / 256, 5), 256>>>(x, Wq, Wk, Wv, Wo,
                                                     xh, Wqh, Wkh, Wvh, Woh,
                                                     nx4, nw4);

    // batched QKV projections, ALL half outputs now
    dim3 gQKV(DIM_ / 128, S_LEN / 128, 3);
    gemm_mma<__half><<<gQKV, 256, GEMM_SMEM>>>(xh, Wqh, Wkh, Wvh, bq, bk, bv,
                                               Qh, Kh, Vh);

    // RMSNorm + RoPE in-place on half Q (pre-scaled) and K, one launch
    rms_rope_kernel<<<dim3(S_LEN, 2), 256>>>(Qh, Kh, gq, gk, Cp, Sn,
                                             0.08838834764831845f);

    // fused attention (proven 256-thread, Q-tile 128)
    dim3 gFlash(S_LEN / 128, NH);
    flash_kernel<<<gFlash, 256, FLASH_SMEM>>>(Qh, Kh, Vh, Oh);

    // out = O @ Wo^T + bo (fp32), proven 128-tile GEMM
    dim3 gO(DIM_ / 128, S_LEN / 128, 1);
    gemm_mma<float><<<gO, 256, GEMM_SMEM>>>(Oh, Woh, Woh, Woh, bo, bo, bo,
                                            out, out, out);
}